// round 4
// baseline (speedup 1.0000x reference)
#include <cuda_runtime.h>
#include <cuda_bf16.h>
#include <cstdint>

#define N_NODES 32768
#define N_EDGES 65536
#define HID 64
#define LN_EPS 1e-5f

// ---------------- scratch (static device globals; no allocation) ----------------
__device__ float g_sum1[N_NODES * HID];
__device__ float g_sum2[N_NODES * HID];
__device__ float g_cnt[N_NODES];
__device__ float g_h1[N_NODES * HID];
__device__ int   g_src[N_EDGES];
__device__ int   g_dst[N_EDGES];

__device__ __forceinline__ int clamp_node(long long v) {
    return v < 0 ? 0 : (v >= N_NODES ? N_NODES - 1 : (int)v);
}

// ---------------- kernel A: edge-index prep (dtype-layout autodetect) ----------
// The harness may deliver edge_index as int64 (as in reference) or converted to
// int32. Detect on-device: interpret the first 8 elements as int64; genuine
// int64 node indices have zero high words. int32 pairs reinterpreted as int64
// are >= 2^32 unless the odd element is 0 (p ~ 2^-15 each).
__global__ void prep_edges(const void* __restrict__ eidx_raw) {
    const long long* p64 = (const long long*)eidx_raw;
    const int*       p32 = (const int*)eidx_raw;
    bool is64 = true;
#pragma unroll
    for (int i = 0; i < 8; i++) {
        long long v = p64[i];            // first 16 int32s: in-bounds either way
        if (v < 0 || v >= N_NODES) { is64 = false; break; }
    }
    int e = blockIdx.x * blockDim.x + threadIdx.x;
    if (e < N_EDGES) {
        long long s, d;
        if (is64) { s = p64[e]; d = p64[N_EDGES + e]; }
        else      { s = p32[e]; d = p32[N_EDGES + e]; }
        g_src[e] = clamp_node(s);
        g_dst[e] = clamp_node(d);
    }
}

// ---------------- kernel 0: zero scratch + output ----------------
__global__ void zero_kernel(float* __restrict__ out) {
    int idx = blockIdx.x * blockDim.x + threadIdx.x;
    if (idx < N_NODES * HID) { g_sum1[idx] = 0.f; g_sum2[idx] = 0.f; }
    if (idx < N_NODES) g_cnt[idx] = 0.f;
    if (idx < HID) out[idx] = 0.f;
}

// ---------------- kernel 1: layer-1 edge MLP + message + scatter ----------------
__global__ void edge_l1_kernel(const float* __restrict__ x,
                               const float* __restrict__ ea,
                               const float* __restrict__ w1,   // [4,64]
                               const float* __restrict__ b1,   // [64]
                               const float* __restrict__ w2,   // [64,256]
                               const float* __restrict__ b2) { // [256]
    int warp = (blockIdx.x * blockDim.x + threadIdx.x) >> 5;
    int lane = threadIdx.x & 31;
    int e0 = warp * 4;
    if (e0 >= N_EDGES) return;

    float hh0[4], hh1[4];
    float4 xs[4];
    int dst[4];
#pragma unroll
    for (int j = 0; j < 4; j++) {
        int e = e0 + j;
        float4 a = __ldg((const float4*)(ea + (size_t)e * 4));
        float v0 = __ldg(&b1[lane])
                 + a.x * __ldg(&w1[lane])       + a.y * __ldg(&w1[64 + lane])
                 + a.z * __ldg(&w1[128 + lane]) + a.w * __ldg(&w1[192 + lane]);
        float v1 = __ldg(&b1[32 + lane])
                 + a.x * __ldg(&w1[32 + lane])  + a.y * __ldg(&w1[96 + lane])
                 + a.z * __ldg(&w1[160 + lane]) + a.w * __ldg(&w1[224 + lane]);
        hh0[j] = fmaxf(v0, 0.f);
        hh1[j] = fmaxf(v1, 0.f);
        int src = g_src[e];
        dst[j]  = g_dst[e];
        xs[j] = __ldg((const float4*)(x + (size_t)src * 4));
    }

    float r[4][8];
#pragma unroll
    for (int t = 0; t < 8; t++) {
        float bb = __ldg(&b2[lane + 32 * t]);
        r[0][t] = bb; r[1][t] = bb; r[2][t] = bb; r[3][t] = bb;
    }

#pragma unroll 4
    for (int k = 0; k < 64; k++) {
        float wv[8];
#pragma unroll
        for (int t = 0; t < 8; t++) wv[t] = __ldg(&w2[k * 256 + lane + 32 * t]);
        float hk[4];
#pragma unroll
        for (int j = 0; j < 4; j++)
            hk[j] = __shfl_sync(0xffffffffu, (k < 32) ? hh0[j] : hh1[j], k & 31);
#pragma unroll
        for (int j = 0; j < 4; j++)
#pragma unroll
            for (int t = 0; t < 8; t++) r[j][t] = fmaf(hk[j], wv[t], r[j][t]);
    }

#pragma unroll
    for (int j = 0; j < 4; j++) {
        float mlo = xs[j].x * r[j][0] + xs[j].y * r[j][2] + xs[j].z * r[j][4] + xs[j].w * r[j][6];
        float mhi = xs[j].x * r[j][1] + xs[j].y * r[j][3] + xs[j].z * r[j][5] + xs[j].w * r[j][7];
        atomicAdd(&g_sum1[(size_t)dst[j] * HID + lane], mlo);
        atomicAdd(&g_sum1[(size_t)dst[j] * HID + 32 + lane], mhi);
        if (lane == 0) atomicAdd(&g_cnt[dst[j]], 1.f);
    }
}

// ---------------- kernel 2: layer-1 node update ----------------
__global__ void node_l1_kernel(const float* __restrict__ x,
                               const float* __restrict__ root1,  // [4,64]
                               const float* __restrict__ bias1,
                               const float* __restrict__ lng,
                               const float* __restrict__ lnb) {
    int warp = (blockIdx.x * blockDim.x + threadIdx.x) >> 5;
    int lane = threadIdx.x & 31;
    int n = warp;
    if (n >= N_NODES) return;

    float inv = 1.f / fmaxf(g_cnt[n], 1.f);
    float4 xv = __ldg((const float4*)(x + (size_t)n * 4));
    float z0 = g_sum1[(size_t)n * HID + lane] * inv + __ldg(&bias1[lane])
             + xv.x * __ldg(&root1[lane])       + xv.y * __ldg(&root1[64 + lane])
             + xv.z * __ldg(&root1[128 + lane]) + xv.w * __ldg(&root1[192 + lane]);
    float z1 = g_sum1[(size_t)n * HID + 32 + lane] * inv + __ldg(&bias1[32 + lane])
             + xv.x * __ldg(&root1[32 + lane])  + xv.y * __ldg(&root1[96 + lane])
             + xv.z * __ldg(&root1[160 + lane]) + xv.w * __ldg(&root1[224 + lane]);
    z0 = fmaxf(z0, 0.f);
    z1 = fmaxf(z1, 0.f);

    float s = z0 + z1;
#pragma unroll
    for (int o = 16; o; o >>= 1) s += __shfl_xor_sync(0xffffffffu, s, o);
    float m = s * (1.f / 64.f);
    float d0 = z0 - m, d1 = z1 - m;
    float v = d0 * d0 + d1 * d1;
#pragma unroll
    for (int o = 16; o; o >>= 1) v += __shfl_xor_sync(0xffffffffu, v, o);
    v *= (1.f / 64.f);
    float is = rsqrtf(v + LN_EPS);
    g_h1[(size_t)n * HID + lane]      = d0 * is * __ldg(&lng[lane])      + __ldg(&lnb[lane]);
    g_h1[(size_t)n * HID + 32 + lane] = d1 * is * __ldg(&lng[32 + lane]) + __ldg(&lnb[32 + lane]);
}

// ---------------- kernel 3: layer-2 (dominant GEMM-shaped kernel) ----------------
// Per CTA: 64 edges. msg[e,o] = sum_{k<128} h2(e,k)*(H1S @ T_k)[e,o] + (H1S @ B)[e,o]
__global__ void __launch_bounds__(256) edge_l2_kernel(
        const float* __restrict__ ea,
        const float* __restrict__ w1,   // e2_w1 [4,128]
        const float* __restrict__ b1,   // [128]
        const float* __restrict__ w2,   // e2_w2 [128,4096]
        const float* __restrict__ b2) { // [4096]
    __shared__ float Tk[4096];      // 16 KB current T_k [i][o]
    __shared__ float H1T[4096];     // 16 KB gathered h1[src]^T [i][e]
    __shared__ float w1s[512];
    __shared__ float b1s[128];
    __shared__ int   src_s[64];
    __shared__ int   dst_s[64];

    int tid = threadIdx.x;
    int e_base = blockIdx.x * 64;

    if (tid < 64) {
        src_s[tid] = g_src[e_base + tid];
        dst_s[tid] = g_dst[e_base + tid];
    }
    w1s[tid]       = __ldg(&w1[tid]);
    w1s[256 + tid] = __ldg(&w1[256 + tid]);
    if (tid < 128) b1s[tid] = __ldg(&b1[tid]);

#pragma unroll
    for (int q = 0; q < 4; q++) {
        int idx = (q * 256 + tid) * 4;
        *(float4*)&Tk[idx] = __ldg((const float4*)(w2 + idx));
    }
    __syncthreads();  // src_s visible

    {
        int e  = tid & 63;
        int ic = (tid >> 6) * 16;
        const float4* row = (const float4*)(g_h1 + (size_t)src_s[e] * HID + ic);
#pragma unroll
        for (int q = 0; q < 4; q++) {
            float4 v = row[q];
            H1T[(ic + q * 4 + 0) * 64 + e] = v.x;
            H1T[(ic + q * 4 + 1) * 64 + e] = v.y;
            H1T[(ic + q * 4 + 2) * 64 + e] = v.z;
            H1T[(ic + q * 4 + 3) * 64 + e] = v.w;
        }
    }

    int e0g = (tid >> 4) * 4;
    int o0  = (tid & 15) * 4;

    float4 ae[4];
#pragma unroll
    for (int j = 0; j < 4; j++)
        ae[j] = __ldg((const float4*)(ea + (size_t)(e_base + e0g + j) * 4));

    __syncthreads();  // H1T + T_0 ready

    float acc[4][4];
#pragma unroll
    for (int a = 0; a < 4; a++)
#pragma unroll
        for (int b = 0; b < 4; b++) acc[a][b] = 0.f;

    float4 pre[4];
    for (int k = 0; k < 129; k++) {
        if (k < 128) {
            const float* nsrc = (k + 1 < 128) ? (w2 + (size_t)(k + 1) * 4096) : b2;
#pragma unroll
            for (int q = 0; q < 4; q++)
                pre[q] = __ldg((const float4*)(nsrc + (q * 256 + tid) * 4));
        }

        float hk[4];
        if (k < 128) {
            float c0 = w1s[k], c1 = w1s[128 + k], c2 = w1s[256 + k], c3 = w1s[384 + k];
            float bb = b1s[k];
#pragma unroll
            for (int a = 0; a < 4; a++)
                hk[a] = fmaxf(fmaf(ae[a].w, c3, fmaf(ae[a].z, c2,
                              fmaf(ae[a].y, c1, fmaf(ae[a].x, c0, bb)))), 0.f);
        } else {
            hk[0] = hk[1] = hk[2] = hk[3] = 1.f;
        }

        float p[4][4];
#pragma unroll
        for (int a = 0; a < 4; a++)
#pragma unroll
            for (int b = 0; b < 4; b++) p[a][b] = 0.f;

#pragma unroll 8
        for (int i = 0; i < 64; i++) {
            float4 av = *(const float4*)&H1T[i * 64 + e0g];
            float4 bv = *(const float4*)&Tk[i * 64 + o0];
            p[0][0] = fmaf(av.x, bv.x, p[0][0]); p[0][1] = fmaf(av.x, bv.y, p[0][1]);
            p[0][2] = fmaf(av.x, bv.z, p[0][2]); p[0][3] = fmaf(av.x, bv.w, p[0][3]);
            p[1][0] = fmaf(av.y, bv.x, p[1][0]); p[1][1] = fmaf(av.y, bv.y, p[1][1]);
            p[1][2] = fmaf(av.y, bv.z, p[1][2]); p[1][3] = fmaf(av.y, bv.w, p[1][3]);
            p[2][0] = fmaf(av.z, bv.x, p[2][0]); p[2][1] = fmaf(av.z, bv.y, p[2][1]);
            p[2][2] = fmaf(av.z, bv.z, p[2][2]); p[2][3] = fmaf(av.z, bv.w, p[2][3]);
            p[3][0] = fmaf(av.w, bv.x, p[3][0]); p[3][1] = fmaf(av.w, bv.y, p[3][1]);
            p[3][2] = fmaf(av.w, bv.z, p[3][2]); p[3][3] = fmaf(av.w, bv.w, p[3][3]);
        }

#pragma unroll
        for (int a = 0; a < 4; a++)
#pragma unroll
            for (int b = 0; b < 4; b++) acc[a][b] = fmaf(hk[a], p[a][b], acc[a][b]);

        __syncthreads();
        if (k < 128) {
#pragma unroll
            for (int q = 0; q < 4; q++)
                *(float4*)&Tk[(q * 256 + tid) * 4] = pre[q];
            __syncthreads();
        }
    }

#pragma unroll
    for (int a = 0; a < 4; a++) {
        int d = dst_s[e0g + a];
#pragma unroll
        for (int b = 0; b < 4; b++)
            atomicAdd(&g_sum2[(size_t)d * HID + o0 + b], acc[a][b]);
    }
}

// ---------------- kernel 4: layer-2 node update + LN + global mean pool ------------
__global__ void node_l2_kernel(const float* __restrict__ root2,  // [64,64]
                               const float* __restrict__ bias2,
                               const float* __restrict__ lng,
                               const float* __restrict__ lnb,
                               float* __restrict__ out) {
    __shared__ float rt[4096];
    __shared__ float acc[64];
    int tid = threadIdx.x;
#pragma unroll
    for (int q = 0; q < 16; q++) rt[tid + q * 256] = __ldg(&root2[tid + q * 256]);
    if (tid < 64) acc[tid] = 0.f;
    __syncthreads();

    int warp = tid >> 5, lane = tid & 31;
    int n = blockIdx.x * 8 + warp;

    float a0 = g_h1[(size_t)n * HID + lane];
    float a1 = g_h1[(size_t)n * HID + 32 + lane];
    float inv = 1.f / fmaxf(g_cnt[n], 1.f);
    float z0 = g_sum2[(size_t)n * HID + lane] * inv + __ldg(&bias2[lane]);
    float z1 = g_sum2[(size_t)n * HID + 32 + lane] * inv + __ldg(&bias2[32 + lane]);

#pragma unroll 16
    for (int i = 0; i < 64; i++) {
        float hi = __shfl_sync(0xffffffffu, (i < 32) ? a0 : a1, i & 31);
        z0 = fmaf(hi, rt[i * 64 + lane], z0);
        z1 = fmaf(hi, rt[i * 64 + 32 + lane], z1);
    }
    z0 = fmaxf(z0, 0.f);
    z1 = fmaxf(z1, 0.f);

    float s = z0 + z1;
#pragma unroll
    for (int o = 16; o; o >>= 1) s += __shfl_xor_sync(0xffffffffu, s, o);
    float m = s * (1.f / 64.f);
    float d0 = z0 - m, d1 = z1 - m;
    float v = d0 * d0 + d1 * d1;
#pragma unroll
    for (int o = 16; o; o >>= 1) v += __shfl_xor_sync(0xffffffffu, v, o);
    v *= (1.f / 64.f);
    float is = rsqrtf(v + LN_EPS);
    float y0 = d0 * is * __ldg(&lng[lane])      + __ldg(&lnb[lane]);
    float y1 = d1 * is * __ldg(&lng[32 + lane]) + __ldg(&lnb[32 + lane]);

    atomicAdd(&acc[lane],      y0 * (1.f / (float)N_NODES));
    atomicAdd(&acc[32 + lane], y1 * (1.f / (float)N_NODES));
    __syncthreads();
    if (tid < 64) atomicAdd(&out[tid], acc[tid]);
}

// ---------------- launch: robust input-order resolution ----------------
// Canonical param order:
//  0 x, 1 ea, 2 eidx, 3 batch, 4 e1_w1, 5 e1_b1, 6 e1_w2, 7 e1_b2, 8 root1,
//  9 bias1, 10 ln1_g, 11 ln1_b, 12 e2_w1, 13 e2_b1, 14 e2_w2, 15 e2_b2,
// 16 root2, 17 bias2, 18 ln2_g, 19 ln2_b
static const int EXP_SIZE[20] = {
    131072, 262144, 131072, 32768, 256, 64, 16384, 256, 256, 64, 64, 64,
    512, 128, 524288, 4096, 4096, 64, 64, 64};

static const int PERM_DICT[20]  = {0,1,2,3,4,5,6,7,8,9,10,11,12,13,14,15,16,17,18,19};
static const int PERM_SIG[20]   = {0,1,18,19,2,3,4,5,6,7,8,9,10,11,12,13,14,15,16,17};
static const int PERM_ALPHA[20] = {19,11,12,0,5,3,6,4,17,1,14,13,9,7,10,8,18,2,16,15};

extern "C" void kernel_launch(void* const* d_in, const int* in_sizes, int n_in,
                              void* d_out, int out_size) {
    const int* perm = PERM_DICT;
    const int* cands[3] = {PERM_DICT, PERM_SIG, PERM_ALPHA};
    for (int p = 0; p < 3; p++) {
        bool ok = (n_in >= 20);
        for (int c = 0; ok && c < 20; c++)
            if (in_sizes[cands[p][c]] != EXP_SIZE[c]) ok = false;
        if (ok) { perm = cands[p]; break; }
    }

    const float* x    = (const float*)d_in[perm[0]];
    const float* ea   = (const float*)d_in[perm[1]];
    const void*  eidx = d_in[perm[2]];
    const float* e1_w1 = (const float*)d_in[perm[4]];
    const float* e1_b1 = (const float*)d_in[perm[5]];
    const float* e1_w2 = (const float*)d_in[perm[6]];
    const float* e1_b2 = (const float*)d_in[perm[7]];
    const float* root1 = (const float*)d_in[perm[8]];
    const float* bias1 = (const float*)d_in[perm[9]];
    const float* ln1_g = (const float*)d_in[perm[10]];
    const float* ln1_b = (const float*)d_in[perm[11]];
    const float* e2_w1 = (const float*)d_in[perm[12]];
    const float* e2_b1 = (const float*)d_in[perm[13]];
    const float* e2_w2 = (const float*)d_in[perm[14]];
    const float* e2_b2 = (const float*)d_in[perm[15]];
    const float* root2 = (const float*)d_in[perm[16]];
    const float* bias2 = (const float*)d_in[perm[17]];
    const float* ln2_g = (const float*)d_in[perm[18]];
    const float* ln2_b = (const float*)d_in[perm[19]];
    float* out = (float*)d_out;

    zero_kernel<<<(N_NODES * HID + 255) / 256, 256>>>(out);
    prep_edges<<<N_EDGES / 256, 256>>>(eidx);
    edge_l1_kernel<<<N_EDGES / 32, 256>>>(x, ea, e1_w1, e1_b1, e1_w2, e1_b2);
    node_l1_kernel<<<N_NODES / 8, 256>>>(x, root1, bias1, ln1_g, ln1_b);
    edge_l2_kernel<<<N_EDGES / 64, 256>>>(ea, e2_w1, e2_b1, e2_w2, e2_b2);
    node_l2_kernel<<<N_NODES / 8, 256>>>(root2, bias2, ln2_g, ln2_b, out);
}

// round 5
// speedup vs baseline: 2.0744x; 2.0744x over previous
#include <cuda_runtime.h>
#include <cuda_bf16.h>
#include <cstdint>

#define N_NODES 32768
#define N_EDGES 65536
#define HID 64
#define LN_EPS 1e-5f

// ---------------- scratch (static device globals; no allocation) ----------------
__device__ float g_sum1[N_NODES * HID];
__device__ float g_sum2[N_NODES * HID];
__device__ float g_cnt[N_NODES];
__device__ float g_h1[N_NODES * HID];
__device__ int   g_src[N_EDGES];
__device__ int   g_dst[N_EDGES];

__device__ __forceinline__ int clamp_node(long long v) {
    return v < 0 ? 0 : (v >= N_NODES ? N_NODES - 1 : (int)v);
}

// ---------------- kernel A: edge-index prep (dtype-layout autodetect) ----------
__global__ void prep_edges(const void* __restrict__ eidx_raw) {
    const long long* p64 = (const long long*)eidx_raw;
    const int*       p32 = (const int*)eidx_raw;
    bool is64 = true;
#pragma unroll
    for (int i = 0; i < 8; i++) {
        long long v = p64[i];
        if (v < 0 || v >= N_NODES) { is64 = false; break; }
    }
    int e = blockIdx.x * blockDim.x + threadIdx.x;
    if (e < N_EDGES) {
        long long s, d;
        if (is64) { s = p64[e]; d = p64[N_EDGES + e]; }
        else      { s = p32[e]; d = p32[N_EDGES + e]; }
        g_src[e] = clamp_node(s);
        g_dst[e] = clamp_node(d);
    }
}

// ---------------- kernel 0: zero scratch + output ----------------
__global__ void zero_kernel(float* __restrict__ out) {
    int idx = blockIdx.x * blockDim.x + threadIdx.x;
    if (idx < N_NODES * HID) { g_sum1[idx] = 0.f; g_sum2[idx] = 0.f; }
    if (idx < N_NODES) g_cnt[idx] = 0.f;
    if (idx < HID) out[idx] = 0.f;
}

// ---------------- kernel 1: layer-1 edge MLP + message + scatter ----------------
__global__ void edge_l1_kernel(const float* __restrict__ x,
                               const float* __restrict__ ea,
                               const float* __restrict__ w1,   // [4,64]
                               const float* __restrict__ b1,   // [64]
                               const float* __restrict__ w2,   // [64,256]
                               const float* __restrict__ b2) { // [256]
    int warp = (blockIdx.x * blockDim.x + threadIdx.x) >> 5;
    int lane = threadIdx.x & 31;
    int e0 = warp * 4;
    if (e0 >= N_EDGES) return;

    float hh0[4], hh1[4];
    float4 xs[4];
    int dst[4];
#pragma unroll
    for (int j = 0; j < 4; j++) {
        int e = e0 + j;
        float4 a = __ldg((const float4*)(ea + (size_t)e * 4));
        float v0 = __ldg(&b1[lane])
                 + a.x * __ldg(&w1[lane])       + a.y * __ldg(&w1[64 + lane])
                 + a.z * __ldg(&w1[128 + lane]) + a.w * __ldg(&w1[192 + lane]);
        float v1 = __ldg(&b1[32 + lane])
                 + a.x * __ldg(&w1[32 + lane])  + a.y * __ldg(&w1[96 + lane])
                 + a.z * __ldg(&w1[160 + lane]) + a.w * __ldg(&w1[224 + lane]);
        hh0[j] = fmaxf(v0, 0.f);
        hh1[j] = fmaxf(v1, 0.f);
        int src = g_src[e];
        dst[j]  = g_dst[e];
        xs[j] = __ldg((const float4*)(x + (size_t)src * 4));
    }

    float r[4][8];
#pragma unroll
    for (int t = 0; t < 8; t++) {
        float bb = __ldg(&b2[lane + 32 * t]);
        r[0][t] = bb; r[1][t] = bb; r[2][t] = bb; r[3][t] = bb;
    }

#pragma unroll 4
    for (int k = 0; k < 64; k++) {
        float wv[8];
#pragma unroll
        for (int t = 0; t < 8; t++) wv[t] = __ldg(&w2[k * 256 + lane + 32 * t]);
        float hk[4];
#pragma unroll
        for (int j = 0; j < 4; j++)
            hk[j] = __shfl_sync(0xffffffffu, (k < 32) ? hh0[j] : hh1[j], k & 31);
#pragma unroll
        for (int j = 0; j < 4; j++)
#pragma unroll
            for (int t = 0; t < 8; t++) r[j][t] = fmaf(hk[j], wv[t], r[j][t]);
    }

#pragma unroll
    for (int j = 0; j < 4; j++) {
        float mlo = xs[j].x * r[j][0] + xs[j].y * r[j][2] + xs[j].z * r[j][4] + xs[j].w * r[j][6];
        float mhi = xs[j].x * r[j][1] + xs[j].y * r[j][3] + xs[j].z * r[j][5] + xs[j].w * r[j][7];
        atomicAdd(&g_sum1[(size_t)dst[j] * HID + lane], mlo);
        atomicAdd(&g_sum1[(size_t)dst[j] * HID + 32 + lane], mhi);
        if (lane == 0) atomicAdd(&g_cnt[dst[j]], 1.f);
    }
}

// ---------------- kernel 2: layer-1 node update ----------------
__global__ void node_l1_kernel(const float* __restrict__ x,
                               const float* __restrict__ root1,  // [4,64]
                               const float* __restrict__ bias1,
                               const float* __restrict__ lng,
                               const float* __restrict__ lnb) {
    int warp = (blockIdx.x * blockDim.x + threadIdx.x) >> 5;
    int lane = threadIdx.x & 31;
    int n = warp;
    if (n >= N_NODES) return;

    float inv = 1.f / fmaxf(g_cnt[n], 1.f);
    float4 xv = __ldg((const float4*)(x + (size_t)n * 4));
    float z0 = g_sum1[(size_t)n * HID + lane] * inv + __ldg(&bias1[lane])
             + xv.x * __ldg(&root1[lane])       + xv.y * __ldg(&root1[64 + lane])
             + xv.z * __ldg(&root1[128 + lane]) + xv.w * __ldg(&root1[192 + lane]);
    float z1 = g_sum1[(size_t)n * HID + 32 + lane] * inv + __ldg(&bias1[32 + lane])
             + xv.x * __ldg(&root1[32 + lane])  + xv.y * __ldg(&root1[96 + lane])
             + xv.z * __ldg(&root1[160 + lane]) + xv.w * __ldg(&root1[224 + lane]);
    z0 = fmaxf(z0, 0.f);
    z1 = fmaxf(z1, 0.f);

    float s = z0 + z1;
#pragma unroll
    for (int o = 16; o; o >>= 1) s += __shfl_xor_sync(0xffffffffu, s, o);
    float m = s * (1.f / 64.f);
    float d0 = z0 - m, d1 = z1 - m;
    float v = d0 * d0 + d1 * d1;
#pragma unroll
    for (int o = 16; o; o >>= 1) v += __shfl_xor_sync(0xffffffffu, v, o);
    v *= (1.f / 64.f);
    float is = rsqrtf(v + LN_EPS);
    g_h1[(size_t)n * HID + lane]      = d0 * is * __ldg(&lng[lane])      + __ldg(&lnb[lane]);
    g_h1[(size_t)n * HID + 32 + lane] = d1 * is * __ldg(&lng[32 + lane]) + __ldg(&lnb[32 + lane]);
}

// ---------------- kernel 3: layer-2 on tensor cores -----------------------------
// Per CTA: 128 edges. msg[e,o] = sum_{k<=128} (h2(e,k)*H1[src_e]) @ T_k  (k=128: h=1, T=bias)
// mma.m16n8k16 bf16: M=edges(16/warp), N=outs(64), K=i(64, 4 chunks).
// 3-pass bf16 split: AhiBhi + AhiBlo + AloBhi (residual ~1.5e-5 rel).
#define H1PAD 136
#define TBPAD 68
#define L2_SMEM (128*H1PAD*4 + 2*32*TBPAD*4 + 512*4 + 128*4 + 128*4 + 64)

__device__ __forceinline__ uint32_t bf2_split(float v0, float v1, float& l0, float& l1) {
    __nv_bfloat162 h = __float22bfloat162_rn(make_float2(v0, v1));
    float2 hf = __bfloat1622float2(h);
    l0 = v0 - hf.x; l1 = v1 - hf.y;
    return *reinterpret_cast<uint32_t*>(&h);
}
__device__ __forceinline__ uint32_t bf2_pack(float v0, float v1) {
    __nv_bfloat162 h = __float22bfloat162_rn(make_float2(v0, v1));
    return *reinterpret_cast<uint32_t*>(&h);
}
__device__ __forceinline__ void mma_bf16(float* c,
        uint32_t a0, uint32_t a1, uint32_t a2, uint32_t a3,
        uint32_t b0, uint32_t b1) {
    asm volatile(
        "mma.sync.aligned.m16n8k16.row.col.f32.bf16.bf16.f32 "
        "{%0,%1,%2,%3}, {%4,%5,%6,%7}, {%8,%9}, {%0,%1,%2,%3};\n"
        : "+f"(c[0]), "+f"(c[1]), "+f"(c[2]), "+f"(c[3])
        : "r"(a0), "r"(a1), "r"(a2), "r"(a3), "r"(b0), "r"(b1));
}

extern __shared__ unsigned char l2_smem[];

__global__ void __launch_bounds__(256, 2) edge_l2_tc(
        const float* __restrict__ ea,
        const float* __restrict__ w1,   // e2_w1 [4,128]
        const float* __restrict__ b1,   // [128]
        const float* __restrict__ w2,   // e2_w2 [128,4096]  ([k][i][o])
        const float* __restrict__ b2) { // [4096]            ([i][o])
    float*    H1f  = (float*)l2_smem;                     // [128][H1PAD] fp32
    uint32_t* TBhi = (uint32_t*)(H1f + 128 * H1PAD);      // [32 ipair][TBPAD o] packed bf16x2
    uint32_t* TBlo = TBhi + 32 * TBPAD;
    float*    w1s  = (float*)(TBlo + 32 * TBPAD);         // [512]
    float*    b1s  = w1s + 512;                           // [128]
    int*      dst_s = (int*)(b1s + 128);                  // [128]

    int tid = threadIdx.x;
    int eb  = blockIdx.x * 128;

    w1s[tid]       = __ldg(&w1[tid]);
    w1s[256 + tid] = __ldg(&w1[256 + tid]);
    if (tid < 128) { b1s[tid] = __ldg(&b1[tid]); dst_s[tid] = g_dst[eb + tid]; }

    // gather H1[src] (fp32): 2 threads per edge, 32 floats each
    {
        int e = tid >> 1, ib = (tid & 1) * 32;
        const float4* rp = (const float4*)(g_h1 + (size_t)g_src[eb + e] * HID + ib);
        float* dp = H1f + e * H1PAD + ib;
#pragma unroll
        for (int q = 0; q < 8; q++) {
            float4 v = rp[q];
            dp[q * 4 + 0] = v.x; dp[q * 4 + 1] = v.y;
            dp[q * 4 + 2] = v.z; dp[q * 4 + 3] = v.w;
        }
    }

    // T staging assignment: thread covers i-rows (2*i2, 2*i2+1), o in [ob, ob+8)
    int i2 = tid >> 3, ob = (tid & 7) * 8;

    // prologue: stage T_0 split into TBhi/TBlo
    {
        const float* src = w2;
        float4 A0 = __ldg((const float4*)(src + (2 * i2) * 64 + ob));
        float4 A1 = __ldg((const float4*)(src + (2 * i2) * 64 + ob + 4));
        float4 B0 = __ldg((const float4*)(src + (2 * i2 + 1) * 64 + ob));
        float4 B1 = __ldg((const float4*)(src + (2 * i2 + 1) * 64 + ob + 4));
        float aa[8] = {A0.x, A0.y, A0.z, A0.w, A1.x, A1.y, A1.z, A1.w};
        float bbv[8] = {B0.x, B0.y, B0.z, B0.w, B1.x, B1.y, B1.z, B1.w};
#pragma unroll
        for (int j = 0; j < 8; j++) {
            float la, lb;
            TBhi[i2 * TBPAD + ob + j] = bf2_split(aa[j], bbv[j], la, lb);
            TBlo[i2 * TBPAD + ob + j] = bf2_pack(la, lb);
        }
    }
    __syncthreads();

    int lane = tid & 31, gID = lane >> 2, tig = lane & 3;
    int wb = (tid >> 5) * 16;           // warp edge base within CTA
    int er0 = wb + gID, er1 = wb + gID + 8;

    float4 ae0 = __ldg((const float4*)(ea + (size_t)(eb + er0) * 4));
    float4 ae1 = __ldg((const float4*)(ea + (size_t)(eb + er1) * 4));

    float acc[8][4];
#pragma unroll
    for (int nt = 0; nt < 8; nt++)
#pragma unroll
        for (int q = 0; q < 4; q++) acc[nt][q] = 0.f;

    float pfa[8], pfb[8];
    for (int k = 0; k <= 128; k++) {
        // prefetch next tile (k+1) into registers
        if (k < 128) {
            const float* nsrc = (k < 127) ? (w2 + (size_t)(k + 1) * 4096) : b2;
            float4 A0 = __ldg((const float4*)(nsrc + (2 * i2) * 64 + ob));
            float4 A1 = __ldg((const float4*)(nsrc + (2 * i2) * 64 + ob + 4));
            float4 B0 = __ldg((const float4*)(nsrc + (2 * i2 + 1) * 64 + ob));
            float4 B1 = __ldg((const float4*)(nsrc + (2 * i2 + 1) * 64 + ob + 4));
            pfa[0]=A0.x; pfa[1]=A0.y; pfa[2]=A0.z; pfa[3]=A0.w;
            pfa[4]=A1.x; pfa[5]=A1.y; pfa[6]=A1.z; pfa[7]=A1.w;
            pfb[0]=B0.x; pfb[1]=B0.y; pfb[2]=B0.z; pfb[3]=B0.w;
            pfb[4]=B1.x; pfb[5]=B1.y; pfb[6]=B1.z; pfb[7]=B1.w;
        }

        float h0, h1;
        if (k < 128) {
            float c0 = w1s[k], c1 = w1s[128 + k], c2 = w1s[256 + k], c3 = w1s[384 + k];
            float bb = b1s[k];
            h0 = fmaxf(fmaf(ae0.w, c3, fmaf(ae0.z, c2, fmaf(ae0.y, c1, fmaf(ae0.x, c0, bb)))), 0.f);
            h1 = fmaxf(fmaf(ae1.w, c3, fmaf(ae1.z, c2, fmaf(ae1.y, c1, fmaf(ae1.x, c0, bb)))), 0.f);
        } else { h0 = 1.f; h1 = 1.f; }

#pragma unroll
        for (int c = 0; c < 4; c++) {
            int ibase = c * 16 + 2 * tig;
            float2 f00 = *(const float2*)&H1f[er0 * H1PAD + ibase];
            float2 f10 = *(const float2*)&H1f[er1 * H1PAD + ibase];
            float2 f01 = *(const float2*)&H1f[er0 * H1PAD + ibase + 8];
            float2 f11 = *(const float2*)&H1f[er1 * H1PAD + ibase + 8];
            float l0a, l1a, l0b, l1b, l0c, l1c, l0d, l1d;
            uint32_t a0h = bf2_split(h0 * f00.x, h0 * f00.y, l0a, l1a);
            uint32_t a1h = bf2_split(h1 * f10.x, h1 * f10.y, l0b, l1b);
            uint32_t a2h = bf2_split(h0 * f01.x, h0 * f01.y, l0c, l1c);
            uint32_t a3h = bf2_split(h1 * f11.x, h1 * f11.y, l0d, l1d);
            uint32_t a0l = bf2_pack(l0a, l1a);
            uint32_t a1l = bf2_pack(l0b, l1b);
            uint32_t a2l = bf2_pack(l0c, l1c);
            uint32_t a3l = bf2_pack(l0d, l1d);

            int p0 = c * 8 + tig;
#pragma unroll
            for (int nt = 0; nt < 8; nt++) {
                int o = nt * 8 + gID;
                uint32_t b0h = TBhi[p0 * TBPAD + o];
                uint32_t b1h = TBhi[(p0 + 4) * TBPAD + o];
                uint32_t b0l = TBlo[p0 * TBPAD + o];
                uint32_t b1l = TBlo[(p0 + 4) * TBPAD + o];
                mma_bf16(acc[nt], a0h, a1h, a2h, a3h, b0h, b1h);
                mma_bf16(acc[nt], a0h, a1h, a2h, a3h, b0l, b1l);
                mma_bf16(acc[nt], a0l, a1l, a2l, a3l, b0h, b1h);
            }
        }

        __syncthreads();
        if (k < 128) {
#pragma unroll
            for (int j = 0; j < 8; j++) {
                float la, lb;
                TBhi[i2 * TBPAD + ob + j] = bf2_split(pfa[j], pfb[j], la, lb);
                TBlo[i2 * TBPAD + ob + j] = bf2_pack(la, lb);
            }
            __syncthreads();
        }
    }

    // epilogue: scatter messages (C rows = edges er0/er1, cols = o)
    int d0 = dst_s[er0], d1 = dst_s[er1];
#pragma unroll
    for (int nt = 0; nt < 8; nt++) {
        int o = nt * 8 + 2 * tig;
        atomicAdd(&g_sum2[(size_t)d0 * HID + o],     acc[nt][0]);
        atomicAdd(&g_sum2[(size_t)d0 * HID + o + 1], acc[nt][1]);
        atomicAdd(&g_sum2[(size_t)d1 * HID + o],     acc[nt][2]);
        atomicAdd(&g_sum2[(size_t)d1 * HID + o + 1], acc[nt][3]);
    }
}

// ---------------- kernel 4: layer-2 node update + LN + global mean pool ------------
__global__ void node_l2_kernel(const float* __restrict__ root2,  // [64,64]
                               const float* __restrict__ bias2,
                               const float* __restrict__ lng,
                               const float* __restrict__ lnb,
                               float* __restrict__ out) {
    __shared__ float rt[4096];
    __shared__ float acc[64];
    int tid = threadIdx.x;
#pragma unroll
    for (int q = 0; q < 16; q++) rt[tid + q * 256] = __ldg(&root2[tid + q * 256]);
    if (tid < 64) acc[tid] = 0.f;
    __syncthreads();

    int warp = tid >> 5, lane = tid & 31;
    int n = blockIdx.x * 8 + warp;

    float a0 = g_h1[(size_t)n * HID + lane];
    float a1 = g_h1[(size_t)n * HID + 32 + lane];
    float inv = 1.f / fmaxf(g_cnt[n], 1.f);
    float z0 = g_sum2[(size_t)n * HID + lane] * inv + __ldg(&bias2[lane]);
    float z1 = g_sum2[(size_t)n * HID + 32 + lane] * inv + __ldg(&bias2[32 + lane]);

#pragma unroll 16
    for (int i = 0; i < 64; i++) {
        float hi = __shfl_sync(0xffffffffu, (i < 32) ? a0 : a1, i & 31);
        z0 = fmaf(hi, rt[i * 64 + lane], z0);
        z1 = fmaf(hi, rt[i * 64 + 32 + lane], z1);
    }
    z0 = fmaxf(z0, 0.f);
    z1 = fmaxf(z1, 0.f);

    float s = z0 + z1;
#pragma unroll
    for (int o = 16; o; o >>= 1) s += __shfl_xor_sync(0xffffffffu, s, o);
    float m = s * (1.f / 64.f);
    float d0 = z0 - m, d1 = z1 - m;
    float v = d0 * d0 + d1 * d1;
#pragma unroll
    for (int o = 16; o; o >>= 1) v += __shfl_xor_sync(0xffffffffu, v, o);
    v *= (1.f / 64.f);
    float is = rsqrtf(v + LN_EPS);
    float y0 = d0 * is * __ldg(&lng[lane])      + __ldg(&lnb[lane]);
    float y1 = d1 * is * __ldg(&lng[32 + lane]) + __ldg(&lnb[32 + lane]);

    atomicAdd(&acc[lane],      y0 * (1.f / (float)N_NODES));
    atomicAdd(&acc[32 + lane], y1 * (1.f / (float)N_NODES));
    __syncthreads();
    if (tid < 64) atomicAdd(&out[tid], acc[tid]);
}

// ---------------- launch: robust input-order resolution ----------------
static const int EXP_SIZE[20] = {
    131072, 262144, 131072, 32768, 256, 64, 16384, 256, 256, 64, 64, 64,
    512, 128, 524288, 4096, 4096, 64, 64, 64};

static const int PERM_DICT[20]  = {0,1,2,3,4,5,6,7,8,9,10,11,12,13,14,15,16,17,18,19};
static const int PERM_SIG[20]   = {0,1,18,19,2,3,4,5,6,7,8,9,10,11,12,13,14,15,16,17};
static const int PERM_ALPHA[20] = {19,11,12,0,5,3,6,4,17,1,14,13,9,7,10,8,18,2,16,15};

extern "C" void kernel_launch(void* const* d_in, const int* in_sizes, int n_in,
                              void* d_out, int out_size) {
    const int* perm = PERM_DICT;
    const int* cands[3] = {PERM_DICT, PERM_SIG, PERM_ALPHA};
    for (int p = 0; p < 3; p++) {
        bool ok = (n_in >= 20);
        for (int c = 0; ok && c < 20; c++)
            if (in_sizes[cands[p][c]] != EXP_SIZE[c]) ok = false;
        if (ok) { perm = cands[p]; break; }
    }

    const float* x    = (const float*)d_in[perm[0]];
    const float* ea   = (const float*)d_in[perm[1]];
    const void*  eidx = d_in[perm[2]];
    const float* e1_w1 = (const float*)d_in[perm[4]];
    const float* e1_b1 = (const float*)d_in[perm[5]];
    const float* e1_w2 = (const float*)d_in[perm[6]];
    const float* e1_b2 = (const float*)d_in[perm[7]];
    const float* root1 = (const float*)d_in[perm[8]];
    const float* bias1 = (const float*)d_in[perm[9]];
    const float* ln1_g = (const float*)d_in[perm[10]];
    const float* ln1_b = (const float*)d_in[perm[11]];
    const float* e2_w1 = (const float*)d_in[perm[12]];
    const float* e2_b1 = (const float*)d_in[perm[13]];
    const float* e2_w2 = (const float*)d_in[perm[14]];
    const float* e2_b2 = (const float*)d_in[perm[15]];
    const float* root2 = (const float*)d_in[perm[16]];
    const float* bias2 = (const float*)d_in[perm[17]];
    const float* ln2_g = (const float*)d_in[perm[18]];
    const float* ln2_b = (const float*)d_in[perm[19]];
    float* out = (float*)d_out;

    static int smem_set = 0;
    if (!smem_set) {
        cudaFuncSetAttribute(edge_l2_tc, cudaFuncAttributeMaxDynamicSharedMemorySize, L2_SMEM);
        smem_set = 1;
    }

    zero_kernel<<<(N_NODES * HID + 255) / 256, 256>>>(out);
    prep_edges<<<N_EDGES / 256, 256>>>(eidx);
    edge_l1_kernel<<<N_EDGES / 32, 256>>>(x, ea, e1_w1, e1_b1, e1_w2, e1_b2);
    node_l1_kernel<<<N_NODES / 8, 256>>>(x, root1, bias1, ln1_g, ln1_b);
    edge_l2_tc<<<N_EDGES / 128, 256, L2_SMEM>>>(ea, e2_w1, e2_b1, e2_w2, e2_b2);
    node_l2_kernel<<<N_NODES / 8, 256>>>(root2, bias2, ln2_g, ln2_b, out);
}

// round 6
// speedup vs baseline: 2.6364x; 1.2710x over previous
#include <cuda_runtime.h>
#include <cuda_bf16.h>
#include <cstdint>

#define N_NODES 32768
#define N_EDGES 65536
#define HID 64
#define LN_EPS 1e-5f

// ---------------- scratch (static device globals; no allocation) ----------------
__device__ float g_sum1[N_NODES * HID];
__device__ float g_sum2[N_NODES * HID];
__device__ float g_cnt[N_NODES];
__device__ float g_h1[N_NODES * HID];
__device__ int   g_src[N_EDGES];
__device__ int   g_dst[N_EDGES];
// pre-split layer-2 weights, transposed: [k=0..128][o=0..63][i=0..63] bf16,
// packed as u32 pairs (i even/odd): index k*2048 + o*32 + i/2. k==128 -> bias b2.
__device__ uint32_t g_Whi[129 * 2048];
__device__ uint32_t g_Wlo[129 * 2048];

__device__ __forceinline__ int clamp_node(long long v) {
    return v < 0 ? 0 : (v >= N_NODES ? N_NODES - 1 : (int)v);
}

__device__ __forceinline__ uint32_t bf2_split(float v0, float v1, float& l0, float& l1) {
    __nv_bfloat162 h = __float22bfloat162_rn(make_float2(v0, v1));
    float2 hf = __bfloat1622float2(h);
    l0 = v0 - hf.x; l1 = v1 - hf.y;
    return *reinterpret_cast<uint32_t*>(&h);
}
__device__ __forceinline__ uint32_t bf2_pack(float v0, float v1) {
    __nv_bfloat162 h = __float22bfloat162_rn(make_float2(v0, v1));
    return *reinterpret_cast<uint32_t*>(&h);
}
__device__ __forceinline__ void mma_bf16(float* c,
        uint32_t a0, uint32_t a1, uint32_t a2, uint32_t a3,
        uint32_t b0, uint32_t b1) {
    asm volatile(
        "mma.sync.aligned.m16n8k16.row.col.f32.bf16.bf16.f32 "
        "{%0,%1,%2,%3}, {%4,%5,%6,%7}, {%8,%9}, {%0,%1,%2,%3};\n"
        : "+f"(c[0]), "+f"(c[1]), "+f"(c[2]), "+f"(c[3])
        : "r"(a0), "r"(a1), "r"(a2), "r"(a3), "r"(b0), "r"(b1));
}
__device__ __forceinline__ void ldsm_x4(uint32_t& r0, uint32_t& r1,
                                        uint32_t& r2, uint32_t& r3, uint32_t saddr) {
    asm volatile("ldmatrix.sync.aligned.m8n8.x4.shared.b16 {%0,%1,%2,%3}, [%4];\n"
        : "=r"(r0), "=r"(r1), "=r"(r2), "=r"(r3) : "r"(saddr));
}

// ---------------- kernel A: edge-index prep (dtype-layout autodetect) ----------
__global__ void prep_edges(const void* __restrict__ eidx_raw) {
    const long long* p64 = (const long long*)eidx_raw;
    const int*       p32 = (const int*)eidx_raw;
    bool is64 = true;
#pragma unroll
    for (int i = 0; i < 8; i++) {
        long long v = p64[i];
        if (v < 0 || v >= N_NODES) { is64 = false; break; }
    }
    int e = blockIdx.x * blockDim.x + threadIdx.x;
    if (e < N_EDGES) {
        long long s, d;
        if (is64) { s = p64[e]; d = p64[N_EDGES + e]; }
        else      { s = p32[e]; d = p32[N_EDGES + e]; }
        g_src[e] = clamp_node(s);
        g_dst[e] = clamp_node(d);
    }
}

// ---------------- kernel B: pre-split + transpose w2 (and b2 as k=128) ---------
// block = one k (129 blocks), thread = one o (64 threads). Reads coalesced across o.
__global__ void split_w2(const float* __restrict__ w2, const float* __restrict__ b2) {
    int k = blockIdx.x;
    int o = threadIdx.x;
    const float* src = (k < 128) ? (w2 + (size_t)k * 4096) : b2;
    size_t base = (size_t)k * 2048 + o * 32;
#pragma unroll 8
    for (int j = 0; j < 32; j++) {
        float v0 = src[(2 * j) * 64 + o];
        float v1 = src[(2 * j + 1) * 64 + o];
        float l0, l1;
        uint32_t hi = bf2_split(v0, v1, l0, l1);
        uint32_t lo = bf2_pack(l0, l1);
        g_Whi[base + j] = hi;
        g_Wlo[base + j] = lo;
    }
}

// ---------------- kernel 0: zero scratch + output ----------------
__global__ void zero_kernel(float* __restrict__ out) {
    int idx = blockIdx.x * blockDim.x + threadIdx.x;
    if (idx < N_NODES * HID) { g_sum1[idx] = 0.f; g_sum2[idx] = 0.f; }
    if (idx < N_NODES) g_cnt[idx] = 0.f;
    if (idx < HID) out[idx] = 0.f;
}

// ---------------- kernel 1: layer-1 edge MLP + message + scatter ----------------
__global__ void edge_l1_kernel(const float* __restrict__ x,
                               const float* __restrict__ ea,
                               const float* __restrict__ w1,   // [4,64]
                               const float* __restrict__ b1,   // [64]
                               const float* __restrict__ w2,   // [64,256]
                               const float* __restrict__ b2) { // [256]
    int warp = (blockIdx.x * blockDim.x + threadIdx.x) >> 5;
    int lane = threadIdx.x & 31;
    int e0 = warp * 4;
    if (e0 >= N_EDGES) return;

    float hh0[4], hh1[4];
    float4 xs[4];
    int dst[4];
#pragma unroll
    for (int j = 0; j < 4; j++) {
        int e = e0 + j;
        float4 a = __ldg((const float4*)(ea + (size_t)e * 4));
        float v0 = __ldg(&b1[lane])
                 + a.x * __ldg(&w1[lane])       + a.y * __ldg(&w1[64 + lane])
                 + a.z * __ldg(&w1[128 + lane]) + a.w * __ldg(&w1[192 + lane]);
        float v1 = __ldg(&b1[32 + lane])
                 + a.x * __ldg(&w1[32 + lane])  + a.y * __ldg(&w1[96 + lane])
                 + a.z * __ldg(&w1[160 + lane]) + a.w * __ldg(&w1[224 + lane]);
        hh0[j] = fmaxf(v0, 0.f);
        hh1[j] = fmaxf(v1, 0.f);
        int src = g_src[e];
        dst[j]  = g_dst[e];
        xs[j] = __ldg((const float4*)(x + (size_t)src * 4));
    }

    float r[4][8];
#pragma unroll
    for (int t = 0; t < 8; t++) {
        float bb = __ldg(&b2[lane + 32 * t]);
        r[0][t] = bb; r[1][t] = bb; r[2][t] = bb; r[3][t] = bb;
    }

#pragma unroll 4
    for (int k = 0; k < 64; k++) {
        float wv[8];
#pragma unroll
        for (int t = 0; t < 8; t++) wv[t] = __ldg(&w2[k * 256 + lane + 32 * t]);
        float hk[4];
#pragma unroll
        for (int j = 0; j < 4; j++)
            hk[j] = __shfl_sync(0xffffffffu, (k < 32) ? hh0[j] : hh1[j], k & 31);
#pragma unroll
        for (int j = 0; j < 4; j++)
#pragma unroll
            for (int t = 0; t < 8; t++) r[j][t] = fmaf(hk[j], wv[t], r[j][t]);
    }

#pragma unroll
    for (int j = 0; j < 4; j++) {
        float mlo = xs[j].x * r[j][0] + xs[j].y * r[j][2] + xs[j].z * r[j][4] + xs[j].w * r[j][6];
        float mhi = xs[j].x * r[j][1] + xs[j].y * r[j][3] + xs[j].z * r[j][5] + xs[j].w * r[j][7];
        atomicAdd(&g_sum1[(size_t)dst[j] * HID + lane], mlo);
        atomicAdd(&g_sum1[(size_t)dst[j] * HID + 32 + lane], mhi);
        if (lane == 0) atomicAdd(&g_cnt[dst[j]], 1.f);
    }
}

// ---------------- kernel 2: layer-1 node update ----------------
__global__ void node_l1_kernel(const float* __restrict__ x,
                               const float* __restrict__ root1,  // [4,64]
                               const float* __restrict__ bias1,
                               const float* __restrict__ lng,
                               const float* __restrict__ lnb) {
    int warp = (blockIdx.x * blockDim.x + threadIdx.x) >> 5;
    int lane = threadIdx.x & 31;
    int n = warp;
    if (n >= N_NODES) return;

    float inv = 1.f / fmaxf(g_cnt[n], 1.f);
    float4 xv = __ldg((const float4*)(x + (size_t)n * 4));
    float z0 = g_sum1[(size_t)n * HID + lane] * inv + __ldg(&bias1[lane])
             + xv.x * __ldg(&root1[lane])       + xv.y * __ldg(&root1[64 + lane])
             + xv.z * __ldg(&root1[128 + lane]) + xv.w * __ldg(&root1[192 + lane]);
    float z1 = g_sum1[(size_t)n * HID + 32 + lane] * inv + __ldg(&bias1[32 + lane])
             + xv.x * __ldg(&root1[32 + lane])  + xv.y * __ldg(&root1[96 + lane])
             + xv.z * __ldg(&root1[160 + lane]) + xv.w * __ldg(&root1[224 + lane]);
    z0 = fmaxf(z0, 0.f);
    z1 = fmaxf(z1, 0.f);

    float s = z0 + z1;
#pragma unroll
    for (int o = 16; o; o >>= 1) s += __shfl_xor_sync(0xffffffffu, s, o);
    float m = s * (1.f / 64.f);
    float d0 = z0 - m, d1 = z1 - m;
    float v = d0 * d0 + d1 * d1;
#pragma unroll
    for (int o = 16; o; o >>= 1) v += __shfl_xor_sync(0xffffffffu, v, o);
    v *= (1.f / 64.f);
    float is = rsqrtf(v + LN_EPS);
    g_h1[(size_t)n * HID + lane]      = d0 * is * __ldg(&lng[lane])      + __ldg(&lnb[lane]);
    g_h1[(size_t)n * HID + 32 + lane] = d1 * is * __ldg(&lng[32 + lane]) + __ldg(&lnb[32 + lane]);
}

// ---------------- kernel 3: layer-2 tensor-core kernel (v2) ----------------------
// 128 edges/CTA, 8 warps, M=16 edges/warp, N=64 outs, 3-pass bf16 split.
// B (=T_k hi/lo) pre-split+transposed in global; staged per-k via LDG.128/STS.128
// into XOR-swizzled smem; fragments loaded with ldmatrix.x4 (conflict-free).
// A (=h2(e,k)*H1[src]) elements live in registers; per-k scale+split only.
__global__ void __launch_bounds__(256, 2) edge_l2_tc(
        const float* __restrict__ ea,
        const float* __restrict__ w1,   // e2_w1 [4,128]
        const float* __restrict__ b1) { // [128]
    __shared__ uint32_t SB[2][2][2048];   // [buf][hi/lo][o*32 + swz] : 32 KB
    __shared__ float w1s[512];
    __shared__ float b1s[128];
    __shared__ int   dst_s[128];

    int tid = threadIdx.x;
    int eb  = blockIdx.x * 128;

    w1s[tid]       = __ldg(&w1[tid]);
    w1s[256 + tid] = __ldg(&w1[256 + tid]);
    if (tid < 128) { b1s[tid] = __ldg(&b1[tid]); dst_s[tid] = g_dst[eb + tid]; }

    // ---- gather H1[src] into smem overlay (transient; exactly fills SB) ----
    float* H1f = (float*)SB;   // [128 e][64 i]
    {
        int e = tid >> 1, ib = (tid & 1) * 32;
        const float4* rp = (const float4*)(g_h1 + (size_t)g_src[eb + e] * HID + ib);
        float4* dp = (float4*)(H1f + e * HID + ib);
#pragma unroll
        for (int q = 0; q < 8; q++) dp[q] = __ldg(&rp[q]);
    }
    __syncthreads();

    int lane = tid & 31, gID = lane >> 2, tig = lane & 3;
    int wb = (tid >> 5) * 16;
    int er0 = wb + gID, er1 = wb + 8 + gID;

    // this lane's 32 A-operand elements (fp32) -> registers
    float A32[32];
#pragma unroll
    for (int c = 0; c < 4; c++) {
        int i0 = c * 16 + 2 * tig;
        float2 t;
        t = *(const float2*)&H1f[er0 * HID + i0];     A32[c*8+0]=t.x; A32[c*8+1]=t.y;
        t = *(const float2*)&H1f[er1 * HID + i0];     A32[c*8+2]=t.x; A32[c*8+3]=t.y;
        t = *(const float2*)&H1f[er0 * HID + i0 + 8]; A32[c*8+4]=t.x; A32[c*8+5]=t.y;
        t = *(const float2*)&H1f[er1 * HID + i0 + 8]; A32[c*8+6]=t.x; A32[c*8+7]=t.y;
    }
    float4 ae0 = __ldg((const float4*)(ea + (size_t)(eb + er0) * 4));
    float4 ae1 = __ldg((const float4*)(ea + (size_t)(eb + er1) * 4));
    __syncthreads();   // H1 overlay region now free for B buffers

    // ---- stage k=0 into buf 0 ----
    {
#pragma unroll
        for (int h = 0; h < 2; h++) {
            const uint32_t* gW = h ? g_Wlo : g_Whi;
#pragma unroll
            for (int q = 0; q < 2; q++) {
                int unit = tid * 2 + q;            // 0..511 (16B units)
                int o = unit >> 3, ch = unit & 7;
                uint4 v = __ldg((const uint4*)(gW + unit * 4));
                *(uint4*)&SB[0][h][o * 32 + ((ch ^ (o & 7)) << 2)] = v;
            }
        }
    }
    __syncthreads();

    uint32_t sbase = (uint32_t)__cvta_generic_to_shared(&SB[0][0][0]);

    float acc[8][4];
#pragma unroll
    for (int nt = 0; nt < 8; nt++)
#pragma unroll
        for (int q = 0; q < 4; q++) acc[nt][q] = 0.f;

    // precompute lane-invariant parts of ldmatrix addressing
    int lm_m = lane >> 3, lm_r = lane & 7;

    for (int k = 0; k <= 128; k++) {
        int buf = k & 1;
        // stage k+1 into the other buffer
        if (k < 128) {
#pragma unroll
            for (int h = 0; h < 2; h++) {
                const uint32_t* gW = (h ? g_Wlo : g_Whi) + (size_t)(k + 1) * 2048;
#pragma unroll
                for (int q = 0; q < 2; q++) {
                    int unit = tid * 2 + q;
                    int o = unit >> 3, ch = unit & 7;
                    uint4 v = __ldg((const uint4*)(gW + unit * 4));
                    *(uint4*)&SB[buf ^ 1][h][o * 32 + ((ch ^ (o & 7)) << 2)] = v;
                }
            }
        }

        float h0, h1;
        if (k < 128) {
            float c0 = w1s[k], c1 = w1s[128 + k], c2 = w1s[256 + k], c3 = w1s[384 + k];
            float bb = b1s[k];
            h0 = fmaxf(fmaf(ae0.w, c3, fmaf(ae0.z, c2, fmaf(ae0.y, c1, fmaf(ae0.x, c0, bb)))), 0.f);
            h1 = fmaxf(fmaf(ae1.w, c3, fmaf(ae1.z, c2, fmaf(ae1.y, c1, fmaf(ae1.x, c0, bb)))), 0.f);
        } else { h0 = 1.f; h1 = 1.f; }

        uint32_t bh = sbase + (uint32_t)(buf * 2 + 0) * 8192;  // 2048 u32 = 8192 B
        uint32_t bl = sbase + (uint32_t)(buf * 2 + 1) * 8192;

#pragma unroll
        for (int c = 0; c < 4; c++) {
            float l0, l1;
            uint32_t a0h = bf2_split(h0 * A32[c*8+0], h0 * A32[c*8+1], l0, l1);
            uint32_t a0l = bf2_pack(l0, l1);
            uint32_t a1h = bf2_split(h1 * A32[c*8+2], h1 * A32[c*8+3], l0, l1);
            uint32_t a1l = bf2_pack(l0, l1);
            uint32_t a2h = bf2_split(h0 * A32[c*8+4], h0 * A32[c*8+5], l0, l1);
            uint32_t a2l = bf2_pack(l0, l1);
            uint32_t a3h = bf2_split(h1 * A32[c*8+6], h1 * A32[c*8+7], l0, l1);
            uint32_t a3l = bf2_pack(l0, l1);

#pragma unroll
            for (int ntp = 0; ntp < 4; ntp++) {
                int o  = (ntp * 2 + (lm_m >> 1)) * 8 + lm_r;
                int ch = c * 2 + (lm_m & 1);
                uint32_t off = (uint32_t)(o * 32 + ((ch ^ (o & 7)) << 2)) << 2;
                uint32_t r0, r1, r2, r3, s0, s1, s2, s3;
                ldsm_x4(r0, r1, r2, r3, bh + off);
                ldsm_x4(s0, s1, s2, s3, bl + off);
                int nt = ntp * 2;
                mma_bf16(acc[nt],     a0h, a1h, a2h, a3h, r0, r1);
                mma_bf16(acc[nt],     a0h, a1h, a2h, a3h, s0, s1);
                mma_bf16(acc[nt],     a0l, a1l, a2l, a3l, r0, r1);
                mma_bf16(acc[nt + 1], a0h, a1h, a2h, a3h, r2, r3);
                mma_bf16(acc[nt + 1], a0h, a1h, a2h, a3h, s2, s3);
                mma_bf16(acc[nt + 1], a0l, a1l, a2l, a3l, r2, r3);
            }
        }
        __syncthreads();
    }

    // ---- epilogue: scatter messages ----
    int d0 = dst_s[er0], d1 = dst_s[er1];
#pragma unroll
    for (int nt = 0; nt < 8; nt++) {
        int o = nt * 8 + 2 * tig;
        atomicAdd(&g_sum2[(size_t)d0 * HID + o],     acc[nt][0]);
        atomicAdd(&g_sum2[(size_t)d0 * HID + o + 1], acc[nt][1]);
        atomicAdd(&g_sum2[(size_t)d1 * HID + o],     acc[nt][2]);
        atomicAdd(&g_sum2[(size_t)d1 * HID + o + 1], acc[nt][3]);
    }
}

// ---------------- kernel 4: layer-2 node update + LN + global mean pool ------------
__global__ void node_l2_kernel(const float* __restrict__ root2,  // [64,64]
                               const float* __restrict__ bias2,
                               const float* __restrict__ lng,
                               const float* __restrict__ lnb,
                               float* __restrict__ out) {
    __shared__ float rt[4096];
    __shared__ float acc[64];
    int tid = threadIdx.x;
#pragma unroll
    for (int q = 0; q < 16; q++) rt[tid + q * 256] = __ldg(&root2[tid + q * 256]);
    if (tid < 64) acc[tid] = 0.f;
    __syncthreads();

    int warp = tid >> 5, lane = tid & 31;
    int n = blockIdx.x * 8 + warp;

    float a0 = g_h1[(size_t)n * HID + lane];
    float a1 = g_h1[(size_t)n * HID + 32 + lane];
    float inv = 1.f / fmaxf(g_cnt[n], 1.f);
    float z0 = g_sum2[(size_t)n * HID + lane] * inv + __ldg(&bias2[lane]);
    float z1 = g_sum2[(size_t)n * HID + 32 + lane] * inv + __ldg(&bias2[32 + lane]);

#pragma unroll 16
    for (int i = 0; i < 64; i++) {
        float hi = __shfl_sync(0xffffffffu, (i < 32) ? a0 : a1, i & 31);
        z0 = fmaf(hi, rt[i * 64 + lane], z0);
        z1 = fmaf(hi, rt[i * 64 + 32 + lane], z1);
    }
    z0 = fmaxf(z0, 0.f);
    z1 = fmaxf(z1, 0.f);

    float s = z0 + z1;
#pragma unroll
    for (int o = 16; o; o >>= 1) s += __shfl_xor_sync(0xffffffffu, s, o);
    float m = s * (1.f / 64.f);
    float d0 = z0 - m, d1 = z1 - m;
    float v = d0 * d0 + d1 * d1;
#pragma unroll
    for (int o = 16; o; o >>= 1) v += __shfl_xor_sync(0xffffffffu, v, o);
    v *= (1.f / 64.f);
    float is = rsqrtf(v + LN_EPS);
    float y0 = d0 * is * __ldg(&lng[lane])      + __ldg(&lnb[lane]);
    float y1 = d1 * is * __ldg(&lng[32 + lane]) + __ldg(&lnb[32 + lane]);

    atomicAdd(&acc[lane],      y0 * (1.f / (float)N_NODES));
    atomicAdd(&acc[32 + lane], y1 * (1.f / (float)N_NODES));
    __syncthreads();
    if (tid < 64) atomicAdd(&out[tid], acc[tid]);
}

// ---------------- launch: robust input-order resolution ----------------
static const int EXP_SIZE[20] = {
    131072, 262144, 131072, 32768, 256, 64, 16384, 256, 256, 64, 64, 64,
    512, 128, 524288, 4096, 4096, 64, 64, 64};

static const int PERM_DICT[20]  = {0,1,2,3,4,5,6,7,8,9,10,11,12,13,14,15,16,17,18,19};
static const int PERM_SIG[20]   = {0,1,18,19,2,3,4,5,6,7,8,9,10,11,12,13,14,15,16,17};
static const int PERM_ALPHA[20] = {19,11,12,0,5,3,6,4,17,1,14,13,9,7,10,8,18,2,16,15};

extern "C" void kernel_launch(void* const* d_in, const int* in_sizes, int n_in,
                              void* d_out, int out_size) {
    const int* perm = PERM_DICT;
    const int* cands[3] = {PERM_DICT, PERM_SIG, PERM_ALPHA};
    for (int p = 0; p < 3; p++) {
        bool ok = (n_in >= 20);
        for (int c = 0; ok && c < 20; c++)
            if (in_sizes[cands[p][c]] != EXP_SIZE[c]) ok = false;
        if (ok) { perm = cands[p]; break; }
    }

    const float* x    = (const float*)d_in[perm[0]];
    const float* ea   = (const float*)d_in[perm[1]];
    const void*  eidx = d_in[perm[2]];
    const float* e1_w1 = (const float*)d_in[perm[4]];
    const float* e1_b1 = (const float*)d_in[perm[5]];
    const float* e1_w2 = (const float*)d_in[perm[6]];
    const float* e1_b2 = (const float*)d_in[perm[7]];
    const float* root1 = (const float*)d_in[perm[8]];
    const float* bias1 = (const float*)d_in[perm[9]];
    const float* ln1_g = (const float*)d_in[perm[10]];
    const float* ln1_b = (const float*)d_in[perm[11]];
    const float* e2_w1 = (const float*)d_in[perm[12]];
    const float* e2_b1 = (const float*)d_in[perm[13]];
    const float* e2_w2 = (const float*)d_in[perm[14]];
    const float* e2_b2 = (const float*)d_in[perm[15]];
    const float* root2 = (const float*)d_in[perm[16]];
    const float* bias2 = (const float*)d_in[perm[17]];
    const float* ln2_g = (const float*)d_in[perm[18]];
    const float* ln2_b = (const float*)d_in[perm[19]];
    float* out = (float*)d_out;

    zero_kernel<<<(N_NODES * HID + 255) / 256, 256>>>(out);
    prep_edges<<<N_EDGES / 256, 256>>>(eidx);
    split_w2<<<129, 64>>>(e2_w2, e2_b2);
    edge_l1_kernel<<<N_EDGES / 32, 256>>>(x, ea, e1_w1, e1_b1, e1_w2, e1_b2);
    node_l1_kernel<<<N_NODES / 8, 256>>>(x, root1, bias1, ln1_g, ln1_b);
    edge_l2_tc<<<N_EDGES / 128, 256>>>(ea, e2_w1, e2_b1);
    node_l2_kernel<<<N_NODES / 8, 256>>>(root2, bias2, ln2_g, ln2_b, out);
}

// round 7
// speedup vs baseline: 3.0276x; 1.1484x over previous
#include <cuda_runtime.h>
#include <cuda_bf16.h>
#include <cstdint>

#define N_NODES 32768
#define N_EDGES 65536
#define HID 64
#define LN_EPS 1e-5f

// ---------------- scratch (static device globals; no allocation) ----------------
__device__ float g_sum1[N_NODES * HID];
__device__ float g_sum2[N_NODES * HID];
__device__ float g_cnt[N_NODES];
__device__ float g_h1[N_NODES * HID];
__device__ int   g_src[N_EDGES];
__device__ int   g_dst[N_EDGES];
// pre-split layer-2 weights, transposed: [k=0..128][o=0..63][i=0..63] bf16,
// packed as u32 pairs (i even/odd): index k*2048 + o*32 + i/2. k==128 -> bias b2.
__device__ uint32_t g_Whi[129 * 2048];
__device__ uint32_t g_Wlo[129 * 2048];

__device__ __forceinline__ int clamp_node(long long v) {
    return v < 0 ? 0 : (v >= N_NODES ? N_NODES - 1 : (int)v);
}

__device__ __forceinline__ uint32_t bf2_split(float v0, float v1, float& l0, float& l1) {
    __nv_bfloat162 h = __float22bfloat162_rn(make_float2(v0, v1));
    float2 hf = __bfloat1622float2(h);
    l0 = v0 - hf.x; l1 = v1 - hf.y;
    return *reinterpret_cast<uint32_t*>(&h);
}
__device__ __forceinline__ uint32_t bf2_pack(float v0, float v1) {
    __nv_bfloat162 h = __float22bfloat162_rn(make_float2(v0, v1));
    return *reinterpret_cast<uint32_t*>(&h);
}
__device__ __forceinline__ void mma_bf16(float* c,
        uint32_t a0, uint32_t a1, uint32_t a2, uint32_t a3,
        uint32_t b0, uint32_t b1) {
    asm volatile(
        "mma.sync.aligned.m16n8k16.row.col.f32.bf16.bf16.f32 "
        "{%0,%1,%2,%3}, {%4,%5,%6,%7}, {%8,%9}, {%0,%1,%2,%3};\n"
        : "+f"(c[0]), "+f"(c[1]), "+f"(c[2]), "+f"(c[3])
        : "r"(a0), "r"(a1), "r"(a2), "r"(a3), "r"(b0), "r"(b1));
}
// first MMA of a chain: C input forced to zero (initializes P for free)
__device__ __forceinline__ void mma_bf16_zc(float* c,
        uint32_t a0, uint32_t a1, uint32_t a2, uint32_t a3,
        uint32_t b0, uint32_t b1) {
    asm volatile(
        "mma.sync.aligned.m16n8k16.row.col.f32.bf16.bf16.f32 "
        "{%0,%1,%2,%3}, {%4,%5,%6,%7}, {%8,%9}, {%10,%11,%12,%13};\n"
        : "=f"(c[0]), "=f"(c[1]), "=f"(c[2]), "=f"(c[3])
        : "r"(a0), "r"(a1), "r"(a2), "r"(a3), "r"(b0), "r"(b1),
          "f"(0.f), "f"(0.f), "f"(0.f), "f"(0.f));
}
__device__ __forceinline__ void ldsm_x4(uint32_t& r0, uint32_t& r1,
                                        uint32_t& r2, uint32_t& r3, uint32_t saddr) {
    asm volatile("ldmatrix.sync.aligned.m8n8.x4.shared.b16 {%0,%1,%2,%3}, [%4];\n"
        : "=r"(r0), "=r"(r1), "=r"(r2), "=r"(r3) : "r"(saddr));
}

// ---------------- kernel A: edge-index prep (dtype-layout autodetect) ----------
__global__ void prep_edges(const void* __restrict__ eidx_raw) {
    const long long* p64 = (const long long*)eidx_raw;
    const int*       p32 = (const int*)eidx_raw;
    bool is64 = true;
#pragma unroll
    for (int i = 0; i < 8; i++) {
        long long v = p64[i];
        if (v < 0 || v >= N_NODES) { is64 = false; break; }
    }
    int e = blockIdx.x * blockDim.x + threadIdx.x;
    if (e < N_EDGES) {
        long long s, d;
        if (is64) { s = p64[e]; d = p64[N_EDGES + e]; }
        else      { s = p32[e]; d = p32[N_EDGES + e]; }
        g_src[e] = clamp_node(s);
        g_dst[e] = clamp_node(d);
    }
}

// ---------------- kernel B: pre-split + transpose w2 (and b2 as k=128) ---------
// 129 blocks x 256 threads; o = tid&63 -> coalesced reads across lanes.
__global__ void split_w2(const float* __restrict__ w2, const float* __restrict__ b2) {
    int k = blockIdx.x;
    int o = threadIdx.x & 63;
    int q = threadIdx.x >> 6;      // 0..3 -> j block
    const float* src = (k < 128) ? (w2 + (size_t)k * 4096) : b2;
    size_t base = (size_t)k * 2048 + o * 32;
#pragma unroll
    for (int jj = 0; jj < 8; jj++) {
        int j = q * 8 + jj;
        float v0 = __ldg(&src[(2 * j) * 64 + o]);
        float v1 = __ldg(&src[(2 * j + 1) * 64 + o]);
        float l0, l1;
        uint32_t hi = bf2_split(v0, v1, l0, l1);
        uint32_t lo = bf2_pack(l0, l1);
        g_Whi[base + j] = hi;
        g_Wlo[base + j] = lo;
    }
}

// ---------------- kernel 0: zero scratch + output ----------------
__global__ void zero_kernel(float* __restrict__ out) {
    int idx = blockIdx.x * blockDim.x + threadIdx.x;
    if (idx < N_NODES * HID) { g_sum1[idx] = 0.f; g_sum2[idx] = 0.f; }
    if (idx < N_NODES) g_cnt[idx] = 0.f;
    if (idx < HID) out[idx] = 0.f;
}

// ---------------- kernel 1: layer-1 edge MLP + message + scatter ----------------
// 8 edges per warp (halves per-edge w2 LDG traffic vs 4/warp).
__global__ void __launch_bounds__(256) edge_l1_kernel(
                               const float* __restrict__ x,
                               const float* __restrict__ ea,
                               const float* __restrict__ w1,   // [4,64]
                               const float* __restrict__ b1,   // [64]
                               const float* __restrict__ w2,   // [64,256]
                               const float* __restrict__ b2) { // [256]
    int warp = (blockIdx.x * blockDim.x + threadIdx.x) >> 5;
    int lane = threadIdx.x & 31;
    int e0 = warp * 8;
    if (e0 >= N_EDGES) return;

    float hh0[8], hh1[8];
#pragma unroll
    for (int j = 0; j < 8; j++) {
        float4 a = __ldg((const float4*)(ea + (size_t)(e0 + j) * 4));
        float v0 = __ldg(&b1[lane])
                 + a.x * __ldg(&w1[lane])       + a.y * __ldg(&w1[64 + lane])
                 + a.z * __ldg(&w1[128 + lane]) + a.w * __ldg(&w1[192 + lane]);
        float v1 = __ldg(&b1[32 + lane])
                 + a.x * __ldg(&w1[32 + lane])  + a.y * __ldg(&w1[96 + lane])
                 + a.z * __ldg(&w1[160 + lane]) + a.w * __ldg(&w1[224 + lane]);
        hh0[j] = fmaxf(v0, 0.f);
        hh1[j] = fmaxf(v1, 0.f);
    }

    float r[8][8];
#pragma unroll
    for (int t = 0; t < 8; t++) {
        float bb = __ldg(&b2[lane + 32 * t]);
#pragma unroll
        for (int j = 0; j < 8; j++) r[j][t] = bb;
    }

#pragma unroll 2
    for (int k = 0; k < 64; k++) {
        float wv[8];
#pragma unroll
        for (int t = 0; t < 8; t++) wv[t] = __ldg(&w2[k * 256 + lane + 32 * t]);
        float hk[8];
#pragma unroll
        for (int j = 0; j < 8; j++)
            hk[j] = __shfl_sync(0xffffffffu, (k < 32) ? hh0[j] : hh1[j], k & 31);
#pragma unroll
        for (int j = 0; j < 8; j++)
#pragma unroll
            for (int t = 0; t < 8; t++) r[j][t] = fmaf(hk[j], wv[t], r[j][t]);
    }

#pragma unroll
    for (int j = 0; j < 8; j++) {
        int e = e0 + j;
        int src = g_src[e], dst = g_dst[e];
        float4 xv = __ldg((const float4*)(x + (size_t)src * 4));
        float mlo = xv.x * r[j][0] + xv.y * r[j][2] + xv.z * r[j][4] + xv.w * r[j][6];
        float mhi = xv.x * r[j][1] + xv.y * r[j][3] + xv.z * r[j][5] + xv.w * r[j][7];
        atomicAdd(&g_sum1[(size_t)dst * HID + lane], mlo);
        atomicAdd(&g_sum1[(size_t)dst * HID + 32 + lane], mhi);
        if (lane == 0) atomicAdd(&g_cnt[dst], 1.f);
    }
}

// ---------------- kernel 2: layer-1 node update ----------------
__global__ void node_l1_kernel(const float* __restrict__ x,
                               const float* __restrict__ root1,  // [4,64]
                               const float* __restrict__ bias1,
                               const float* __restrict__ lng,
                               const float* __restrict__ lnb) {
    int warp = (blockIdx.x * blockDim.x + threadIdx.x) >> 5;
    int lane = threadIdx.x & 31;
    int n = warp;
    if (n >= N_NODES) return;

    float inv = 1.f / fmaxf(g_cnt[n], 1.f);
    float4 xv = __ldg((const float4*)(x + (size_t)n * 4));
    float z0 = g_sum1[(size_t)n * HID + lane] * inv + __ldg(&bias1[lane])
             + xv.x * __ldg(&root1[lane])       + xv.y * __ldg(&root1[64 + lane])
             + xv.z * __ldg(&root1[128 + lane]) + xv.w * __ldg(&root1[192 + lane]);
    float z1 = g_sum1[(size_t)n * HID + 32 + lane] * inv + __ldg(&bias1[32 + lane])
             + xv.x * __ldg(&root1[32 + lane])  + xv.y * __ldg(&root1[96 + lane])
             + xv.z * __ldg(&root1[160 + lane]) + xv.w * __ldg(&root1[224 + lane]);
    z0 = fmaxf(z0, 0.f);
    z1 = fmaxf(z1, 0.f);

    float s = z0 + z1;
#pragma unroll
    for (int o = 16; o; o >>= 1) s += __shfl_xor_sync(0xffffffffu, s, o);
    float m = s * (1.f / 64.f);
    float d0 = z0 - m, d1 = z1 - m;
    float v = d0 * d0 + d1 * d1;
#pragma unroll
    for (int o = 16; o; o >>= 1) v += __shfl_xor_sync(0xffffffffu, v, o);
    v *= (1.f / 64.f);
    float is = rsqrtf(v + LN_EPS);
    g_h1[(size_t)n * HID + lane]      = d0 * is * __ldg(&lng[lane])      + __ldg(&lnb[lane]);
    g_h1[(size_t)n * HID + 32 + lane] = d1 * is * __ldg(&lng[32 + lane]) + __ldg(&lnb[32 + lane]);
}

// ---------------- kernel 3: layer-2 tensor-core kernel (v3: P-structure) --------
// Per CTA 128 edges, 8 warps (M=16/warp). A = H1[src] split into bf16 hi/lo ONCE
// (k-invariant, registers). Per k: P = A @ T_k via 3-pass MMA (zero-C init),
// then acc += h2(e,k) * P (32 scalar FFMA). B staged per-k (pre-split global ->
// swizzled smem, double-buffered), fragments via ldmatrix.
__global__ void __launch_bounds__(256, 2) edge_l2_tc(
        const float* __restrict__ ea,
        const float* __restrict__ w1,   // e2_w1 [4,128]
        const float* __restrict__ b1) { // [128]
    __shared__ uint32_t SB[2][2][2048];   // [buf][hi/lo][o*32 + swz] : 32 KB
    __shared__ float w1s[512];
    __shared__ float b1s[128];
    __shared__ int   dst_s[128];

    int tid = threadIdx.x;
    int eb  = blockIdx.x * 128;

    w1s[tid]       = __ldg(&w1[tid]);
    w1s[256 + tid] = __ldg(&w1[256 + tid]);
    if (tid < 128) { b1s[tid] = __ldg(&b1[tid]); dst_s[tid] = g_dst[eb + tid]; }

    int lane = tid & 31, gID = lane >> 2, tig = lane & 3;
    int wb = (tid >> 5) * 16;
    int er0 = wb + gID, er1 = wb + 8 + gID;

    // ---- direct gather H1[src] -> registers, pre-split to bf16 hi/lo ----
    uint32_t Ahi[4][4], Alo[4][4];
    {
        const float* r0p = g_h1 + (size_t)g_src[eb + er0] * HID;
        const float* r1p = g_h1 + (size_t)g_src[eb + er1] * HID;
#pragma unroll
        for (int c = 0; c < 4; c++) {
            int i0 = c * 16 + 2 * tig;
            float2 x0 = __ldg((const float2*)(r0p + i0));
            float2 x1 = __ldg((const float2*)(r1p + i0));
            float2 x2 = __ldg((const float2*)(r0p + i0 + 8));
            float2 x3 = __ldg((const float2*)(r1p + i0 + 8));
            float l0, l1;
            Ahi[c][0] = bf2_split(x0.x, x0.y, l0, l1); Alo[c][0] = bf2_pack(l0, l1);
            Ahi[c][1] = bf2_split(x1.x, x1.y, l0, l1); Alo[c][1] = bf2_pack(l0, l1);
            Ahi[c][2] = bf2_split(x2.x, x2.y, l0, l1); Alo[c][2] = bf2_pack(l0, l1);
            Ahi[c][3] = bf2_split(x3.x, x3.y, l0, l1); Alo[c][3] = bf2_pack(l0, l1);
        }
    }
    float4 ae0 = __ldg((const float4*)(ea + (size_t)(eb + er0) * 4));
    float4 ae1 = __ldg((const float4*)(ea + (size_t)(eb + er1) * 4));

    // ---- stage k=0 into buf 0 ----
#pragma unroll
    for (int h = 0; h < 2; h++) {
        const uint32_t* gW = h ? g_Wlo : g_Whi;
#pragma unroll
        for (int q = 0; q < 2; q++) {
            int unit = tid * 2 + q;            // 0..511 (16B units)
            int o = unit >> 3, ch = unit & 7;
            uint4 v = __ldg((const uint4*)(gW + unit * 4));
            *(uint4*)&SB[0][h][o * 32 + ((ch ^ (o & 7)) << 2)] = v;
        }
    }
    __syncthreads();

    uint32_t sbase = (uint32_t)__cvta_generic_to_shared(&SB[0][0][0]);

    float acc[8][4];
#pragma unroll
    for (int nt = 0; nt < 8; nt++)
#pragma unroll
        for (int q = 0; q < 4; q++) acc[nt][q] = 0.f;

    int lm_m = lane >> 3, lm_r = lane & 7;

    for (int k = 0; k <= 128; k++) {
        int buf = k & 1;
        // load next tile into registers (STS deferred to after compute)
        uint4 v[4];
        if (k < 128) {
#pragma unroll
            for (int h = 0; h < 2; h++) {
                const uint32_t* gW = (h ? g_Wlo : g_Whi) + (size_t)(k + 1) * 2048;
#pragma unroll
                for (int q = 0; q < 2; q++)
                    v[h * 2 + q] = __ldg((const uint4*)(gW + (tid * 2 + q) * 4));
            }
        }

        float h0, h1;
        if (k < 128) {
            float c0 = w1s[k], c1 = w1s[128 + k], c2 = w1s[256 + k], c3 = w1s[384 + k];
            float bb = b1s[k];
            h0 = fmaxf(fmaf(ae0.w, c3, fmaf(ae0.z, c2, fmaf(ae0.y, c1, fmaf(ae0.x, c0, bb)))), 0.f);
            h1 = fmaxf(fmaf(ae1.w, c3, fmaf(ae1.z, c2, fmaf(ae1.y, c1, fmaf(ae1.x, c0, bb)))), 0.f);
        } else { h0 = 1.f; h1 = 1.f; }

        uint32_t bh = sbase + (uint32_t)(buf * 2 + 0) * 8192;
        uint32_t bl = sbase + (uint32_t)(buf * 2 + 1) * 8192;

#pragma unroll
        for (int ntp = 0; ntp < 4; ntp++) {
            float pe[4], po[4];
#pragma unroll
            for (int c = 0; c < 4; c++) {
                int o  = (ntp * 2 + (lm_m >> 1)) * 8 + lm_r;
                int ch = c * 2 + (lm_m & 1);
                uint32_t off = (uint32_t)(o * 32 + ((ch ^ (o & 7)) << 2)) << 2;
                uint32_t r0, r1, r2, r3, s0, s1, s2, s3;
                ldsm_x4(r0, r1, r2, r3, bh + off);
                ldsm_x4(s0, s1, s2, s3, bl + off);
                if (c == 0) {
                    mma_bf16_zc(pe, Ahi[0][0], Ahi[0][1], Ahi[0][2], Ahi[0][3], r0, r1);
                    mma_bf16_zc(po, Ahi[0][0], Ahi[0][1], Ahi[0][2], Ahi[0][3], r2, r3);
                } else {
                    mma_bf16(pe, Ahi[c][0], Ahi[c][1], Ahi[c][2], Ahi[c][3], r0, r1);
                    mma_bf16(po, Ahi[c][0], Ahi[c][1], Ahi[c][2], Ahi[c][3], r2, r3);
                }
                mma_bf16(pe, Ahi[c][0], Ahi[c][1], Ahi[c][2], Ahi[c][3], s0, s1);
                mma_bf16(pe, Alo[c][0], Alo[c][1], Alo[c][2], Alo[c][3], r0, r1);
                mma_bf16(po, Ahi[c][0], Ahi[c][1], Ahi[c][2], Ahi[c][3], s2, s3);
                mma_bf16(po, Alo[c][0], Alo[c][1], Alo[c][2], Alo[c][3], r2, r3);
            }
            int nt = ntp * 2;
            acc[nt][0]     = fmaf(h0, pe[0], acc[nt][0]);
            acc[nt][1]     = fmaf(h0, pe[1], acc[nt][1]);
            acc[nt][2]     = fmaf(h1, pe[2], acc[nt][2]);
            acc[nt][3]     = fmaf(h1, pe[3], acc[nt][3]);
            acc[nt + 1][0] = fmaf(h0, po[0], acc[nt + 1][0]);
            acc[nt + 1][1] = fmaf(h0, po[1], acc[nt + 1][1]);
            acc[nt + 1][2] = fmaf(h1, po[2], acc[nt + 1][2]);
            acc[nt + 1][3] = fmaf(h1, po[3], acc[nt + 1][3]);
        }

        if (k < 128) {
#pragma unroll
            for (int h = 0; h < 2; h++)
#pragma unroll
                for (int q = 0; q < 2; q++) {
                    int unit = tid * 2 + q;
                    int o = unit >> 3, ch = unit & 7;
                    *(uint4*)&SB[buf ^ 1][h][o * 32 + ((ch ^ (o & 7)) << 2)] = v[h * 2 + q];
                }
        }
        __syncthreads();
    }

    // ---- epilogue: scatter messages ----
    int d0 = dst_s[er0], d1 = dst_s[er1];
#pragma unroll
    for (int nt = 0; nt < 8; nt++) {
        int o = nt * 8 + 2 * tig;
        atomicAdd(&g_sum2[(size_t)d0 * HID + o],     acc[nt][0]);
        atomicAdd(&g_sum2[(size_t)d0 * HID + o + 1], acc[nt][1]);
        atomicAdd(&g_sum2[(size_t)d1 * HID + o],     acc[nt][2]);
        atomicAdd(&g_sum2[(size_t)d1 * HID + o + 1], acc[nt][3]);
    }
}

// ---------------- kernel 4: layer-2 node update + LN + global mean pool ------------
__global__ void node_l2_kernel(const float* __restrict__ root2,  // [64,64]
                               const float* __restrict__ bias2,
                               const float* __restrict__ lng,
                               const float* __restrict__ lnb,
                               float* __restrict__ out) {
    __shared__ float rt[4096];
    __shared__ float acc[64];
    int tid = threadIdx.x;
#pragma unroll
    for (int q = 0; q < 16; q++) rt[tid + q * 256] = __ldg(&root2[tid + q * 256]);
    if (tid < 64) acc[tid] = 0.f;
    __syncthreads();

    int warp = tid >> 5, lane = tid & 31;
    int n = blockIdx.x * 8 + warp;

    float a0 = g_h1[(size_t)n * HID + lane];
    float a1 = g_h1[(size_t)n * HID + 32 + lane];
    float inv = 1.f / fmaxf(g_cnt[n], 1.f);
    float z0 = g_sum2[(size_t)n * HID + lane] * inv + __ldg(&bias2[lane]);
    float z1 = g_sum2[(size_t)n * HID + 32 + lane] * inv + __ldg(&bias2[32 + lane]);

#pragma unroll 16
    for (int i = 0; i < 64; i++) {
        float hi = __shfl_sync(0xffffffffu, (i < 32) ? a0 : a1, i & 31);
        z0 = fmaf(hi, rt[i * 64 + lane], z0);
        z1 = fmaf(hi, rt[i * 64 + 32 + lane], z1);
    }
    z0 = fmaxf(z0, 0.f);
    z1 = fmaxf(z1, 0.f);

    float s = z0 + z1;
#pragma unroll
    for (int o = 16; o; o >>= 1) s += __shfl_xor_sync(0xffffffffu, s, o);
    float m = s * (1.f / 64.f);
    float d0 = z0 - m, d1 = z1 - m;
    float v = d0 * d0 + d1 * d1;
#pragma unroll
    for (int o = 16; o; o >>= 1) v += __shfl_xor_sync(0xffffffffu, v, o);
    v *= (1.f / 64.f);
    float is = rsqrtf(v + LN_EPS);
    float y0 = d0 * is * __ldg(&lng[lane])      + __ldg(&lnb[lane]);
    float y1 = d1 * is * __ldg(&lng[32 + lane]) + __ldg(&lnb[32 + lane]);

    atomicAdd(&acc[lane],      y0 * (1.f / (float)N_NODES));
    atomicAdd(&acc[32 + lane], y1 * (1.f / (float)N_NODES));
    __syncthreads();
    if (tid < 64) atomicAdd(&out[tid], acc[tid]);
}

// ---------------- launch: robust input-order resolution ----------------
static const int EXP_SIZE[20] = {
    131072, 262144, 131072, 32768, 256, 64, 16384, 256, 256, 64, 64, 64,
    512, 128, 524288, 4096, 4096, 64, 64, 64};

static const int PERM_DICT[20]  = {0,1,2,3,4,5,6,7,8,9,10,11,12,13,14,15,16,17,18,19};
static const int PERM_SIG[20]   = {0,1,18,19,2,3,4,5,6,7,8,9,10,11,12,13,14,15,16,17};
static const int PERM_ALPHA[20] = {19,11,12,0,5,3,6,4,17,1,14,13,9,7,10,8,18,2,16,15};

extern "C" void kernel_launch(void* const* d_in, const int* in_sizes, int n_in,
                              void* d_out, int out_size) {
    const int* perm = PERM_DICT;
    const int* cands[3] = {PERM_DICT, PERM_SIG, PERM_ALPHA};
    for (int p = 0; p < 3; p++) {
        bool ok = (n_in >= 20);
        for (int c = 0; ok && c < 20; c++)
            if (in_sizes[cands[p][c]] != EXP_SIZE[c]) ok = false;
        if (ok) { perm = cands[p]; break; }
    }

    const float* x    = (const float*)d_in[perm[0]];
    const float* ea   = (const float*)d_in[perm[1]];
    const void*  eidx = d_in[perm[2]];
    const float* e1_w1 = (const float*)d_in[perm[4]];
    const float* e1_b1 = (const float*)d_in[perm[5]];
    const float* e1_w2 = (const float*)d_in[perm[6]];
    const float* e1_b2 = (const float*)d_in[perm[7]];
    const float* root1 = (const float*)d_in[perm[8]];
    const float* bias1 = (const float*)d_in[perm[9]];
    const float* ln1_g = (const float*)d_in[perm[10]];
    const float* ln1_b = (const float*)d_in[perm[11]];
    const float* e2_w1 = (const float*)d_in[perm[12]];
    const float* e2_b1 = (const float*)d_in[perm[13]];
    const float* e2_w2 = (const float*)d_in[perm[14]];
    const float* e2_b2 = (const float*)d_in[perm[15]];
    const float* root2 = (const float*)d_in[perm[16]];
    const float* bias2 = (const float*)d_in[perm[17]];
    const float* ln2_g = (const float*)d_in[perm[18]];
    const float* ln2_b = (const float*)d_in[perm[19]];
    float* out = (float*)d_out;

    zero_kernel<<<(N_NODES * HID + 255) / 256, 256>>>(out);
    prep_edges<<<N_EDGES / 256, 256>>>(eidx);
    split_w2<<<129, 256>>>(e2_w2, e2_b2);
    edge_l1_kernel<<<N_EDGES / 64, 256>>>(x, ea, e1_w1, e1_b1, e1_w2, e1_b2);
    node_l1_kernel<<<N_NODES / 8, 256>>>(x, root1, bias1, ln1_g, ln1_b);
    edge_l2_tc<<<N_EDGES / 128, 256>>>(ea, e2_w1, e2_b1);
    node_l2_kernel<<<N_NODES / 8, 256>>>(root2, bias2, ln2_g, ln2_b, out);
}